// round 1
// baseline (speedup 1.0000x reference)
#include <cuda_runtime.h>
#include <math.h>

#define B_DIM 8192
#define IN_DIM 1024
#define H_DIM 1024
#define N_DIM 4096   // 4*H
#define K_DIM 2048   // IN + H
#define EPS 1e-6f

// Scratch for the gate pre-activations v = [x|h] @ [w_ih|w_hh]^T  (8192 x 4096 fp32)
__device__ float g_v[(size_t)B_DIM * N_DIM];

// ---------------------------------------------------------------------------
// GEMM: v[b,n] = sum_k A[b,k] * W[n,k],  A = [x | h], W = [w_ih | w_hh]
// Both operands are K-contiguous row-major ("NT" GEMM).
// 128x128 tile, K-tile 16, 256 threads, 8x8 per-thread microtile.
// ---------------------------------------------------------------------------
#define TM 128
#define TN 128
#define TK 16

__global__ __launch_bounds__(256, 2)
void lstm_gemm_kernel(const float* __restrict__ x,
                      const float* __restrict__ h,
                      const float* __restrict__ w_ih,
                      const float* __restrict__ w_hh)
{
    __shared__ float As[TK][TM + 4];
    __shared__ float Bs[TK][TN + 4];

    const int bm = blockIdx.y * TM;
    const int bn = blockIdx.x * TN;
    const int tid = threadIdx.x;
    const int tx = tid & 15;          // 0..15 -> n
    const int ty = tid >> 4;          // 0..15 -> m

    float acc[8][8];
#pragma unroll
    for (int i = 0; i < 8; i++)
#pragma unroll
        for (int j = 0; j < 8; j++)
            acc[i][j] = 0.0f;

    for (int k0 = 0; k0 < K_DIM; k0 += TK) {
        // Load 128x16 A tile and 128x16 B tile.
        // 512 float4 per tile; 256 threads -> 2 float4 each per tile.
#pragma unroll
        for (int r = 0; r < 2; r++) {
            int f   = tid + r * 256;     // 0..511
            int row = f >> 2;            // 0..127
            int q   = f & 3;             // k-quad 0..3
            int gk  = k0 + q * 4;

            float4 av, bv;
            if (gk < IN_DIM) {
                av = *(const float4*)&x   [(size_t)(bm + row) * IN_DIM + gk];
                bv = *(const float4*)&w_ih[(size_t)(bn + row) * IN_DIM + gk];
            } else {
                av = *(const float4*)&h   [(size_t)(bm + row) * H_DIM + (gk - IN_DIM)];
                bv = *(const float4*)&w_hh[(size_t)(bn + row) * H_DIM + (gk - IN_DIM)];
            }
            int kq = q * 4;
            As[kq + 0][row] = av.x; As[kq + 1][row] = av.y;
            As[kq + 2][row] = av.z; As[kq + 3][row] = av.w;
            Bs[kq + 0][row] = bv.x; Bs[kq + 1][row] = bv.y;
            Bs[kq + 2][row] = bv.z; Bs[kq + 3][row] = bv.w;
        }
        __syncthreads();

#pragma unroll
        for (int kk = 0; kk < TK; kk++) {
            float a[8], b[8];
#pragma unroll
            for (int i = 0; i < 8; i++) a[i] = As[kk][ty * 8 + i];
#pragma unroll
            for (int j = 0; j < 8; j++) b[j] = Bs[kk][tx * 8 + j];
#pragma unroll
            for (int i = 0; i < 8; i++)
#pragma unroll
                for (int j = 0; j < 8; j++)
                    acc[i][j] = fmaf(a[i], b[j], acc[i][j]);
        }
        __syncthreads();
    }

    // Store
#pragma unroll
    for (int i = 0; i < 8; i++) {
        int m = bm + ty * 8 + i;
        float* vrow = &g_v[(size_t)m * N_DIM + bn + tx * 8];
#pragma unroll
        for (int j = 0; j < 8; j += 4) {
            float4 o;
            o.x = acc[i][j + 0]; o.y = acc[i][j + 1];
            o.z = acc[i][j + 2]; o.w = acc[i][j + 3];
            *(float4*)&vrow[j] = o;
        }
    }
}

// ---------------------------------------------------------------------------
// Epilogue: per batch row b:
//   gates = reshape(v[b] + b_ih, (4, H)); LN per gate (ddof=1);
//   f += 1; new_c = c*sig(f) + sig(i)*tanh(g); LN(new_c) (ddof=1);
//   new_h = tanh(new_c)*sig(o)
// One CTA (256 threads) per row; each thread owns 4 strided columns per gate.
// ---------------------------------------------------------------------------

__device__ __forceinline__ float sigmoidf_(float v) {
    return 1.0f / (1.0f + expf(-v));
}

// Block reduction of (sum, sumsq) over 256 threads / 8 warps.
__device__ __forceinline__ void block_reduce2(float& s, float& sq,
                                              float* sh, int tid)
{
#pragma unroll
    for (int off = 16; off > 0; off >>= 1) {
        s  += __shfl_down_sync(0xFFFFFFFFu, s,  off);
        sq += __shfl_down_sync(0xFFFFFFFFu, sq, off);
    }
    int warp = tid >> 5, lane = tid & 31;
    if (lane == 0) { sh[warp] = s; sh[8 + warp] = sq; }
    __syncthreads();
    if (tid == 0) {
        float ts = 0.0f, tq = 0.0f;
#pragma unroll
        for (int w = 0; w < 8; w++) { ts += sh[w]; tq += sh[8 + w]; }
        sh[16] = ts; sh[17] = tq;
    }
    __syncthreads();
    s = sh[16]; sq = sh[17];
    __syncthreads();   // protect sh reuse for next reduction
}

__global__ __launch_bounds__(256, 4)
void lstm_epilogue_kernel(const float* __restrict__ c,
                          const float* __restrict__ b_ih,
                          const float* __restrict__ gamma_ifgo,
                          const float* __restrict__ beta_ifgo,
                          const float* __restrict__ gamma_c,
                          const float* __restrict__ beta_c,
                          float* __restrict__ out_h,
                          float* __restrict__ out_c)
{
    __shared__ float sh[18];

    const int b   = blockIdx.x;
    const int tid = threadIdx.x;
    const float* vrow = &g_v[(size_t)b * N_DIM];

    float gate[4][4];   // [gate][element]

    // --- per-gate LayerNorm ---
#pragma unroll
    for (int gi = 0; gi < 4; gi++) {
        float s = 0.0f, sq = 0.0f;
#pragma unroll
        for (int r = 0; r < 4; r++) {
            int col = tid + r * 256;
            float val = vrow[gi * H_DIM + col] + b_ih[gi * H_DIM + col];
            gate[gi][r] = val;
            s += val; sq += val * val;
        }
        block_reduce2(s, sq, sh, tid);
        float mean = s * (1.0f / H_DIM);
        float var  = (sq - (float)H_DIM * mean * mean) * (1.0f / (H_DIM - 1));
        var = fmaxf(var, 0.0f);
        float inv = 1.0f / (sqrtf(var) + EPS);
#pragma unroll
        for (int r = 0; r < 4; r++) {
            int col = tid + r * 256;
            gate[gi][r] = gamma_ifgo[gi * H_DIM + col] * (gate[gi][r] - mean) * inv
                        + beta_ifgo[gi * H_DIM + col];
        }
    }

    // --- LSTM pointwise + cell LayerNorm ---
    float nc[4];
    float og[4];
    {
        float s = 0.0f, sq = 0.0f;
#pragma unroll
        for (int r = 0; r < 4; r++) {
            int col = tid + r * 256;
            float iv = gate[0][r];
            float fv = gate[1][r] + 1.0f;
            float gv = gate[2][r];
            og[r]    = gate[3][r];
            float cv = c[(size_t)b * H_DIM + col];
            float v  = cv * sigmoidf_(fv) + sigmoidf_(iv) * tanhf(gv);
            nc[r] = v;
            s += v; sq += v * v;
        }
        block_reduce2(s, sq, sh, tid);
        float mean = s * (1.0f / H_DIM);
        float var  = (sq - (float)H_DIM * mean * mean) * (1.0f / (H_DIM - 1));
        var = fmaxf(var, 0.0f);
        float inv = 1.0f / (sqrtf(var) + EPS);
#pragma unroll
        for (int r = 0; r < 4; r++) {
            int col = tid + r * 256;
            float ncv = gamma_c[col] * (nc[r] - mean) * inv + beta_c[col];
            out_c[(size_t)b * H_DIM + col] = ncv;
            out_h[(size_t)b * H_DIM + col] = tanhf(ncv) * sigmoidf_(og[r]);
        }
    }
}

// ---------------------------------------------------------------------------
// Launch
// Inputs (metadata order): x, h, c, w_ih, b_ih, w_hh,
//                          gamma_ifgo, beta_ifgo, gamma_c, beta_c
// Output: concat(new_h, new_c), each 8192x1024 fp32.
// ---------------------------------------------------------------------------
extern "C" void kernel_launch(void* const* d_in, const int* in_sizes, int n_in,
                              void* d_out, int out_size)
{
    const float* x          = (const float*)d_in[0];
    const float* h          = (const float*)d_in[1];
    const float* c          = (const float*)d_in[2];
    const float* w_ih       = (const float*)d_in[3];
    const float* b_ih       = (const float*)d_in[4];
    const float* w_hh       = (const float*)d_in[5];
    const float* gamma_ifgo = (const float*)d_in[6];
    const float* beta_ifgo  = (const float*)d_in[7];
    const float* gamma_c    = (const float*)d_in[8];
    const float* beta_c     = (const float*)d_in[9];

    float* out_h = (float*)d_out;
    float* out_c = (float*)d_out + (size_t)B_DIM * H_DIM;

    dim3 grid(N_DIM / TN, B_DIM / TM);   // (32, 64)
    lstm_gemm_kernel<<<grid, 256>>>(x, h, w_ih, w_hh);

    lstm_epilogue_kernel<<<B_DIM, 256>>>(c, b_ih, gamma_ifgo, beta_ifgo,
                                         gamma_c, beta_c, out_h, out_c);
}

// round 3
// speedup vs baseline: 2.7854x; 2.7854x over previous
#include <cuda_runtime.h>
#include <math.h>
#include <stdint.h>

#define B_DIM 8192
#define IN_DIM 1024
#define H_DIM 1024
#define N_DIM 4096
#define K_DIM 2048
#define EPS 1e-6f

// GEMM tiling
#define TM 128
#define TN 256
#define KT 16
#define KTILES (K_DIM / KT)        // 128
#define A_STRIDE 20                // floats per smem row (16 data + 4 pad)
#define A_STAGE_F (TM * A_STRIDE)  // 2560 floats
#define B_STAGE_F (TN * A_STRIDE)  // 5120 floats
#define STAGE_B ((A_STAGE_F + B_STAGE_F) * 4)   // 30720 bytes
#define SMEM_TOTAL (3 * STAGE_B)                // 92160

// Scratch (tf32-rounded operands, packed K=2048) + GEMM output
__device__ float g_A[(size_t)B_DIM * K_DIM];   // 67 MB
__device__ float g_B[(size_t)N_DIM * K_DIM];   // 33 MB
__device__ float g_v[(size_t)B_DIM * N_DIM];   // 134 MB

// ---------------------------------------------------------------------------
// Helpers
// ---------------------------------------------------------------------------
__device__ __forceinline__ uint32_t smem_u32(const void* p) {
    uint32_t a;
    asm("{ .reg .u64 t; cvta.to.shared.u64 t, %1; cvt.u32.u64 %0, t; }"
        : "=r"(a) : "l"(p));
    return a;
}
__device__ __forceinline__ void cp16(uint32_t smem, const void* g) {
    asm volatile("cp.async.cg.shared.global [%0], [%1], 16;"
                 :: "r"(smem), "l"(g));
}
__device__ __forceinline__ float tf32_rna(float v) {
    uint32_t o;
    asm("cvt.rna.tf32.f32 %0, %1;" : "=r"(o) : "f"(v));
    return __uint_as_float(o);
}

#define MMA_TF32(d, a, b)                                                   \
    asm volatile(                                                           \
        "mma.sync.aligned.m16n8k8.row.col.f32.tf32.tf32.f32 "               \
        "{%0,%1,%2,%3}, {%4,%5,%6,%7}, {%8,%9}, {%0,%1,%2,%3};"             \
        : "+f"((d)[0]), "+f"((d)[1]), "+f"((d)[2]), "+f"((d)[3])            \
        : "r"((a)[0]), "r"((a)[1]), "r"((a)[2]), "r"((a)[3]),               \
          "r"((b)[0]), "r"((b)[1]))

// ---------------------------------------------------------------------------
// tf32 conversion pre-pass (rna rounding, pack x|h and w_ih|w_hh, K=2048)
// ---------------------------------------------------------------------------
__global__ __launch_bounds__(256)
void conv_A(const float* __restrict__ x, const float* __restrict__ h)
{
    size_t idx = (size_t)blockIdx.x * 256 + threadIdx.x;  // one float4
    int r = (int)(idx >> 9);
    int k = ((int)idx & 511) * 4;
    const float* src = (k < IN_DIM) ? (x + (size_t)r * IN_DIM + k)
                                    : (h + (size_t)r * H_DIM + (k - IN_DIM));
    float4 v = *(const float4*)src;
    v.x = tf32_rna(v.x); v.y = tf32_rna(v.y);
    v.z = tf32_rna(v.z); v.w = tf32_rna(v.w);
    *(float4*)(g_A + (size_t)r * K_DIM + k) = v;
}

__global__ __launch_bounds__(256)
void conv_B(const float* __restrict__ w_ih, const float* __restrict__ w_hh)
{
    size_t idx = (size_t)blockIdx.x * 256 + threadIdx.x;
    int r = (int)(idx >> 9);
    int k = ((int)idx & 511) * 4;
    const float* src = (k < IN_DIM) ? (w_ih + (size_t)r * IN_DIM + k)
                                    : (w_hh + (size_t)r * H_DIM + (k - IN_DIM));
    float4 v = *(const float4*)src;
    v.x = tf32_rna(v.x); v.y = tf32_rna(v.y);
    v.z = tf32_rna(v.z); v.w = tf32_rna(v.w);
    *(float4*)(g_B + (size_t)r * K_DIM + k) = v;
}

// ---------------------------------------------------------------------------
// tf32 mma.sync GEMM: v = A @ B^T   (M=8192, N=4096, K=2048)
// CTA tile 128x256, k-tile 16, 3-stage cp.async pipeline.
// 8 warps, warp grid 2(M) x 4(N), warp tile 64x64 -> 4x8 m16n8k8 per k-step.
// ---------------------------------------------------------------------------
__device__ __forceinline__ void load_stage(int kt, int s, int tid,
                                           uint32_t sbase, int bm, int bn)
{
    uint32_t sA = sbase + s * STAGE_B;
    uint32_t sB = sA + A_STAGE_F * 4;
    int k0 = kt * KT;
    const float* ga = g_A + (size_t)bm * K_DIM + k0;
    const float* gb = g_B + (size_t)bn * K_DIM + k0;
#pragma unroll
    for (int i = 0; i < 2; i++) {               // A: 512 float4 units
        int u = tid + i * 256;
        int row = u >> 2, q = u & 3;
        cp16(sA + (uint32_t)(row * (A_STRIDE * 4) + q * 16),
             ga + (size_t)row * K_DIM + q * 4);
    }
#pragma unroll
    for (int i = 0; i < 4; i++) {               // B: 1024 float4 units
        int u = tid + i * 256;
        int row = u >> 2, q = u & 3;
        cp16(sB + (uint32_t)(row * (A_STRIDE * 4) + q * 16),
             gb + (size_t)row * K_DIM + q * 4);
    }
    asm volatile("cp.async.commit_group;" ::: "memory");
}

__global__ __launch_bounds__(256, 1)
void lstm_gemm_tf32()
{
    extern __shared__ __align__(128) char smem[];
    uint32_t sbase = smem_u32(smem);
    const int tid = threadIdx.x;
    const int wid = tid >> 5, lane = tid & 31;
    const int g = lane >> 2, c = lane & 3;
    const int warpM = (wid & 1) * 64;
    const int warpN = (wid >> 1) * 64;
    const int bn = blockIdx.x * TN;
    const int bm = blockIdx.y * TM;

    float acc[4][8][4];
#pragma unroll
    for (int mt = 0; mt < 4; mt++)
#pragma unroll
        for (int nt = 0; nt < 8; nt++)
#pragma unroll
            for (int r = 0; r < 4; r++)
                acc[mt][nt][r] = 0.0f;

    load_stage(0, 0, tid, sbase, bm, bn);
    load_stage(1, 1, tid, sbase, bm, bn);

    for (int kt = 0; kt < KTILES; kt++) {
        int s = kt % 3;
        if (kt < KTILES - 1) asm volatile("cp.async.wait_group 1;" ::: "memory");
        else                 asm volatile("cp.async.wait_group 0;" ::: "memory");
        __syncthreads();

        if (kt + 2 < KTILES)
            load_stage(kt + 2, (kt + 2) % 3, tid, sbase, bm, bn);

        const float* As = (const float*)(smem + s * STAGE_B);
        const float* Bs = As + A_STAGE_F;

#pragma unroll
        for (int ks = 0; ks < 2; ks++) {
            int kb = ks * 8;
            uint32_t a[4][4], b[8][2];
#pragma unroll
            for (int mt = 0; mt < 4; mt++) {
                int r0 = warpM + mt * 16 + g;
                a[mt][0] = __float_as_uint(As[r0 * A_STRIDE + kb + c]);
                a[mt][1] = __float_as_uint(As[(r0 + 8) * A_STRIDE + kb + c]);
                a[mt][2] = __float_as_uint(As[r0 * A_STRIDE + kb + c + 4]);
                a[mt][3] = __float_as_uint(As[(r0 + 8) * A_STRIDE + kb + c + 4]);
            }
#pragma unroll
            for (int nt = 0; nt < 8; nt++) {
                int cn = warpN + nt * 8 + g;
                b[nt][0] = __float_as_uint(Bs[cn * A_STRIDE + kb + c]);
                b[nt][1] = __float_as_uint(Bs[cn * A_STRIDE + kb + c + 4]);
            }
#pragma unroll
            for (int mt = 0; mt < 4; mt++)
#pragma unroll
                for (int nt = 0; nt < 8; nt++)
                    MMA_TF32(acc[mt][nt], a[mt], b[nt]);
        }
        __syncthreads();
    }

    // Store C: c0,c1 -> (row g, cols 2c,2c+1); c2,c3 -> row g+8
#pragma unroll
    for (int mt = 0; mt < 4; mt++) {
        int r0 = bm + warpM + mt * 16 + g;
#pragma unroll
        for (int nt = 0; nt < 8; nt++) {
            int cn = bn + warpN + nt * 8 + 2 * c;
            float2 v01 = make_float2(acc[mt][nt][0], acc[mt][nt][1]);
            float2 v23 = make_float2(acc[mt][nt][2], acc[mt][nt][3]);
            *(float2*)(g_v + (size_t)r0 * N_DIM + cn) = v01;
            *(float2*)(g_v + (size_t)(r0 + 8) * N_DIM + cn) = v23;
        }
    }
}

// ---------------------------------------------------------------------------
// Epilogue (MUFU-based activations)
// ---------------------------------------------------------------------------
__device__ __forceinline__ float sigmoidf_(float v) {
    return 1.0f / (1.0f + __expf(-v));
}
__device__ __forceinline__ float tanhf_(float v) {
    return 2.0f / (1.0f + __expf(-2.0f * v)) - 1.0f;
}

__device__ __forceinline__ void block_reduce2(float& s, float& sq,
                                              float* sh, int tid)
{
#pragma unroll
    for (int off = 16; off > 0; off >>= 1) {
        s  += __shfl_down_sync(0xFFFFFFFFu, s,  off);
        sq += __shfl_down_sync(0xFFFFFFFFu, sq, off);
    }
    int warp = tid >> 5, lane = tid & 31;
    if (lane == 0) { sh[warp] = s; sh[8 + warp] = sq; }
    __syncthreads();
    if (tid == 0) {
        float ts = 0.0f, tq = 0.0f;
#pragma unroll
        for (int w = 0; w < 8; w++) { ts += sh[w]; tq += sh[8 + w]; }
        sh[16] = ts; sh[17] = tq;
    }
    __syncthreads();
    s = sh[16]; sq = sh[17];
    __syncthreads();
}

__global__ __launch_bounds__(256, 4)
void lstm_epilogue_kernel(const float* __restrict__ c,
                          const float* __restrict__ b_ih,
                          const float* __restrict__ gamma_ifgo,
                          const float* __restrict__ beta_ifgo,
                          const float* __restrict__ gamma_c,
                          const float* __restrict__ beta_c,
                          float* __restrict__ out_h,
                          float* __restrict__ out_c)
{
    __shared__ float sh[18];

    const int b   = blockIdx.x;
    const int tid = threadIdx.x;
    const float* vrow = &g_v[(size_t)b * N_DIM];

    float gate[4][4];

#pragma unroll
    for (int gi = 0; gi < 4; gi++) {
        float s = 0.0f, sq = 0.0f;
#pragma unroll
        for (int r = 0; r < 4; r++) {
            int col = tid + r * 256;
            float val = vrow[gi * H_DIM + col] + b_ih[gi * H_DIM + col];
            gate[gi][r] = val;
            s += val; sq += val * val;
        }
        block_reduce2(s, sq, sh, tid);
        float mean = s * (1.0f / H_DIM);
        float var  = (sq - (float)H_DIM * mean * mean) * (1.0f / (H_DIM - 1));
        var = fmaxf(var, 0.0f);
        float inv = 1.0f / (sqrtf(var) + EPS);
#pragma unroll
        for (int r = 0; r < 4; r++) {
            int col = tid + r * 256;
            gate[gi][r] = gamma_ifgo[gi * H_DIM + col] * (gate[gi][r] - mean) * inv
                        + beta_ifgo[gi * H_DIM + col];
        }
    }

    float nc[4], og[4];
    {
        float s = 0.0f, sq = 0.0f;
#pragma unroll
        for (int r = 0; r < 4; r++) {
            int col = tid + r * 256;
            float iv = gate[0][r];
            float fv = gate[1][r] + 1.0f;
            float gv = gate[2][r];
            og[r]    = gate[3][r];
            float cv = c[(size_t)b * H_DIM + col];
            float v  = cv * sigmoidf_(fv) + sigmoidf_(iv) * tanhf_(gv);
            nc[r] = v;
            s += v; sq += v * v;
        }
        block_reduce2(s, sq, sh, tid);
        float mean = s * (1.0f / H_DIM);
        float var  = (sq - (float)H_DIM * mean * mean) * (1.0f / (H_DIM - 1));
        var = fmaxf(var, 0.0f);
        float inv = 1.0f / (sqrtf(var) + EPS);
#pragma unroll
        for (int r = 0; r < 4; r++) {
            int col = tid + r * 256;
            float ncv = gamma_c[col] * (nc[r] - mean) * inv + beta_c[col];
            out_c[(size_t)b * H_DIM + col] = ncv;
            out_h[(size_t)b * H_DIM + col] = tanhf_(ncv) * sigmoidf_(og[r]);
        }
    }
}

// ---------------------------------------------------------------------------
// Launch
// ---------------------------------------------------------------------------
extern "C" void kernel_launch(void* const* d_in, const int* in_sizes, int n_in,
                              void* d_out, int out_size)
{
    const float* x          = (const float*)d_in[0];
    const float* h          = (const float*)d_in[1];
    const float* c          = (const float*)d_in[2];
    const float* w_ih       = (const float*)d_in[3];
    const float* b_ih       = (const float*)d_in[4];
    const float* w_hh       = (const float*)d_in[5];
    const float* gamma_ifgo = (const float*)d_in[6];
    const float* beta_ifgo  = (const float*)d_in[7];
    const float* gamma_c    = (const float*)d_in[8];
    const float* beta_c     = (const float*)d_in[9];

    float* out_h = (float*)d_out;
    float* out_c = (float*)d_out + (size_t)B_DIM * H_DIM;

    cudaFuncSetAttribute(lstm_gemm_tf32,
                         cudaFuncAttributeMaxDynamicSharedMemorySize, SMEM_TOTAL);

    conv_A<<<16384, 256>>>(x, h);      // 8192*2048/4 float4 units
    conv_B<<<8192, 256>>>(w_ih, w_hh); // 4096*2048/4

    dim3 grid(N_DIM / TN, B_DIM / TM);  // (16, 64)
    lstm_gemm_tf32<<<grid, 256, SMEM_TOTAL>>>();

    lstm_epilogue_kernel<<<B_DIM, 256>>>(c, b_ih, gamma_ifgo, beta_ifgo,
                                         gamma_c, beta_c, out_h, out_c);
}

// round 4
// speedup vs baseline: 4.9519x; 1.7778x over previous
#include <cuda_runtime.h>
#include <cuda_fp16.h>
#include <math.h>
#include <stdint.h>

#define B_DIM 8192
#define IN_DIM 1024
#define H_DIM 1024
#define N_DIM 4096
#define K_DIM 2048
#define EPS 1e-6f

// GEMM tiling
#define TM 128
#define TN 256
#define KT 32                       // halves per k-tile (2 ksteps of k16)
#define KTILES (K_DIM / KT)         // 64
#define ROW_B 80                    // bytes per smem row: 64 data + 16 pad
#define A_STAGE_B (TM * ROW_B)      // 10240
#define B_STAGE_B (TN * ROW_B)      // 20480
#define STAGE_B (A_STAGE_B + B_STAGE_B)   // 30720
#define SMEM_TOTAL (3 * STAGE_B)          // 92160

// Scratch: fp16 operands (packed K=2048) + fp32 GEMM output
__device__ __half g_A[(size_t)B_DIM * K_DIM];   // 33.5 MB
__device__ __half g_B[(size_t)N_DIM * K_DIM];   // 16.8 MB
__device__ float  g_v[(size_t)B_DIM * N_DIM];   // 134 MB

// ---------------------------------------------------------------------------
// Helpers
// ---------------------------------------------------------------------------
__device__ __forceinline__ uint32_t smem_u32(const void* p) {
    uint32_t a;
    asm("{ .reg .u64 t; cvta.to.shared.u64 t, %1; cvt.u32.u64 %0, t; }"
        : "=r"(a) : "l"(p));
    return a;
}
__device__ __forceinline__ void cp16(uint32_t smem, const void* g) {
    asm volatile("cp.async.cg.shared.global [%0], [%1], 16;"
                 :: "r"(smem), "l"(g));
}
#define LDSM_X4(r0, r1, r2, r3, addr)                                        \
    asm volatile("ldmatrix.sync.aligned.m8n8.x4.shared.b16 {%0,%1,%2,%3}, [%4];" \
                 : "=r"(r0), "=r"(r1), "=r"(r2), "=r"(r3) : "r"(addr))

#define MMA_F16(d, a, b)                                                     \
    asm volatile(                                                            \
        "mma.sync.aligned.m16n8k16.row.col.f32.f16.f16.f32 "                 \
        "{%0,%1,%2,%3}, {%4,%5,%6,%7}, {%8,%9}, {%0,%1,%2,%3};"              \
        : "+f"((d)[0]), "+f"((d)[1]), "+f"((d)[2]), "+f"((d)[3])             \
        : "r"((a)[0]), "r"((a)[1]), "r"((a)[2]), "r"((a)[3]),                \
          "r"((b)[0]), "r"((b)[1]))

// ---------------------------------------------------------------------------
// fp16 conversion pre-pass (pack x|h -> g_A, w_ih|w_hh -> g_B, K=2048)
// ---------------------------------------------------------------------------
__global__ __launch_bounds__(256)
void conv_A(const float* __restrict__ x, const float* __restrict__ h)
{
    size_t idx = (size_t)blockIdx.x * 256 + threadIdx.x;  // one float4 unit
    int r = (int)(idx >> 9);
    int k = ((int)idx & 511) * 4;
    const float* src = (k < IN_DIM) ? (x + (size_t)r * IN_DIM + k)
                                    : (h + (size_t)r * H_DIM + (k - IN_DIM));
    float4 v = *(const float4*)src;
    __half2 lo = __floats2half2_rn(v.x, v.y);
    __half2 hi = __floats2half2_rn(v.z, v.w);
    *(__half2*)(g_A + (size_t)r * K_DIM + k)     = lo;
    *(__half2*)(g_A + (size_t)r * K_DIM + k + 2) = hi;
}

__global__ __launch_bounds__(256)
void conv_B(const float* __restrict__ w_ih, const float* __restrict__ w_hh)
{
    size_t idx = (size_t)blockIdx.x * 256 + threadIdx.x;
    int r = (int)(idx >> 9);
    int k = ((int)idx & 511) * 4;
    const float* src = (k < IN_DIM) ? (w_ih + (size_t)r * IN_DIM + k)
                                    : (w_hh + (size_t)r * H_DIM + (k - IN_DIM));
    float4 v = *(const float4*)src;
    __half2 lo = __floats2half2_rn(v.x, v.y);
    __half2 hi = __floats2half2_rn(v.z, v.w);
    *(__half2*)(g_B + (size_t)r * K_DIM + k)     = lo;
    *(__half2*)(g_B + (size_t)r * K_DIM + k + 2) = hi;
}

// ---------------------------------------------------------------------------
// fp16 mma.sync GEMM: v = A @ B^T   (M=8192, N=4096, K=2048)
// CTA 128x256, KT=32 (2 ksteps), 3-stage cp.async, ldmatrix fragment loads.
// 8 warps, warp grid 2(M) x 4(N), warp tile 64x64 -> 4x8 m16n8k16 per kstep.
// ---------------------------------------------------------------------------
__device__ __forceinline__ void load_stage(int kt, int s, int tid,
                                           uint32_t sbase, int bm, int bn)
{
    uint32_t sA = sbase + s * STAGE_B;
    uint32_t sB = sA + A_STAGE_B;
    int k0 = kt * KT;
    const __half* ga = g_A + (size_t)bm * K_DIM + k0;
    const __half* gb = g_B + (size_t)bn * K_DIM + k0;
#pragma unroll
    for (int i = 0; i < 2; i++) {               // A: 512 16B units
        int u = tid + i * 256;
        int row = u >> 2, q = u & 3;
        cp16(sA + (uint32_t)(row * ROW_B + q * 16),
             ga + (size_t)row * K_DIM + q * 8);
    }
#pragma unroll
    for (int i = 0; i < 4; i++) {               // B: 1024 16B units
        int u = tid + i * 256;
        int row = u >> 2, q = u & 3;
        cp16(sB + (uint32_t)(row * ROW_B + q * 16),
             gb + (size_t)row * K_DIM + q * 8);
    }
    asm volatile("cp.async.commit_group;" ::: "memory");
}

__global__ __launch_bounds__(256, 1)
void lstm_gemm_f16()
{
    extern __shared__ __align__(128) char smem[];
    uint32_t sbase = smem_u32(smem);
    const int tid = threadIdx.x;
    const int wid = tid >> 5, lane = tid & 31;
    const int g = lane >> 2, c = lane & 3;
    const int warpM = (wid & 1) * 64;
    const int warpN = (wid >> 1) * 64;
    const int bn = blockIdx.x * TN;
    const int bm = blockIdx.y * TM;

    // ldmatrix per-lane offsets (bytes within a stage)
    const int q  = lane >> 3;       // 0..3 (matrix index)
    const int rr = lane & 7;        // row within 8x8
    // A x4: mats {rows 0-7 k0-7, rows 8-15 k0-7, rows 0-7 k8-15, rows 8-15 k8-15}
    const uint32_t laneA = (uint32_t)(((q & 1) * 8 + rr) * ROW_B + (q >> 1) * 16);
    // B x4: mats {n 0-7 k0-7, n 0-7 k8-15, n 8-15 k0-7, n 8-15 k8-15}
    const uint32_t laneB = (uint32_t)(((q >> 1) * 8 + rr) * ROW_B + (q & 1) * 16);

    float acc[4][8][4];
#pragma unroll
    for (int mt = 0; mt < 4; mt++)
#pragma unroll
        for (int nt = 0; nt < 8; nt++)
#pragma unroll
            for (int r = 0; r < 4; r++)
                acc[mt][nt][r] = 0.0f;

    load_stage(0, 0, tid, sbase, bm, bn);
    load_stage(1, 1, tid, sbase, bm, bn);

    for (int kt = 0; kt < KTILES; kt++) {
        int s = kt % 3;
        if (kt < KTILES - 1) asm volatile("cp.async.wait_group 1;" ::: "memory");
        else                 asm volatile("cp.async.wait_group 0;" ::: "memory");
        __syncthreads();

        if (kt + 2 < KTILES)
            load_stage(kt + 2, (kt + 2) % 3, tid, sbase, bm, bn);

        uint32_t stA = sbase + s * STAGE_B;
        uint32_t stB = stA + A_STAGE_B;

#pragma unroll
        for (int ks = 0; ks < 2; ks++) {
            uint32_t a[4][4], b[4][4];
#pragma unroll
            for (int mt = 0; mt < 4; mt++) {
                uint32_t addr = stA + (uint32_t)((warpM + mt * 16) * ROW_B
                                                 + ks * 32) + laneA;
                LDSM_X4(a[mt][0], a[mt][1], a[mt][2], a[mt][3], addr);
            }
#pragma unroll
            for (int np = 0; np < 4; np++) {    // pair of n-tiles
                uint32_t addr = stB + (uint32_t)((warpN + np * 16) * ROW_B
                                                 + ks * 32) + laneB;
                // regs: {b0(nt=2np), b1(nt=2np), b0(nt=2np+1), b1(nt=2np+1)}
                LDSM_X4(b[np][0], b[np][1], b[np][2], b[np][3], addr);
            }
#pragma unroll
            for (int mt = 0; mt < 4; mt++)
#pragma unroll
                for (int nt = 0; nt < 8; nt++) {
                    uint32_t bf[2] = { b[nt >> 1][(nt & 1) * 2],
                                       b[nt >> 1][(nt & 1) * 2 + 1] };
                    MMA_F16(acc[mt][nt], a[mt], bf);
                }
        }
        __syncthreads();
    }

    // Store C: c0,c1 -> (row g, cols 2c,2c+1); c2,c3 -> row g+8
#pragma unroll
    for (int mt = 0; mt < 4; mt++) {
        int r0 = bm + warpM + mt * 16 + g;
#pragma unroll
        for (int nt = 0; nt < 8; nt++) {
            int cn = bn + warpN + nt * 8 + 2 * c;
            *(float2*)(g_v + (size_t)r0 * N_DIM + cn)
                = make_float2(acc[mt][nt][0], acc[mt][nt][1]);
            *(float2*)(g_v + (size_t)(r0 + 8) * N_DIM + cn)
                = make_float2(acc[mt][nt][2], acc[mt][nt][3]);
        }
    }
}

// ---------------------------------------------------------------------------
// Epilogue (float4-vectorized, MUFU activations)
// ---------------------------------------------------------------------------
__device__ __forceinline__ float sigmoidf_(float v) {
    return 1.0f / (1.0f + __expf(-v));
}
__device__ __forceinline__ float tanhf_(float v) {
    return 2.0f / (1.0f + __expf(-2.0f * v)) - 1.0f;
}

__device__ __forceinline__ void block_reduce2(float& s, float& sq,
                                              float* sh, int tid)
{
#pragma unroll
    for (int off = 16; off > 0; off >>= 1) {
        s  += __shfl_down_sync(0xFFFFFFFFu, s,  off);
        sq += __shfl_down_sync(0xFFFFFFFFu, sq, off);
    }
    int warp = tid >> 5, lane = tid & 31;
    if (lane == 0) { sh[warp] = s; sh[8 + warp] = sq; }
    __syncthreads();
    if (tid == 0) {
        float ts = 0.0f, tq = 0.0f;
#pragma unroll
        for (int w = 0; w < 8; w++) { ts += sh[w]; tq += sh[8 + w]; }
        sh[16] = ts; sh[17] = tq;
    }
    __syncthreads();
    s = sh[16]; sq = sh[17];
    __syncthreads();
}

__global__ __launch_bounds__(256, 4)
void lstm_epilogue_kernel(const float* __restrict__ c,
                          const float* __restrict__ b_ih,
                          const float* __restrict__ gamma_ifgo,
                          const float* __restrict__ beta_ifgo,
                          const float* __restrict__ gamma_c,
                          const float* __restrict__ beta_c,
                          float* __restrict__ out_h,
                          float* __restrict__ out_c)
{
    __shared__ float sh[18];

    const int b   = blockIdx.x;
    const int tid = threadIdx.x;
    const float4* vrow = (const float4*)&g_v[(size_t)b * N_DIM];  // 1024 float4
    const float4* bih4 = (const float4*)b_ih;
    const float4* gam4 = (const float4*)gamma_ifgo;
    const float4* bet4 = (const float4*)beta_ifgo;

    float gate[4][4];

#pragma unroll
    for (int gi = 0; gi < 4; gi++) {
        float4 v  = vrow[gi * 256 + tid];
        float4 bi = bih4[gi * 256 + tid];
        gate[gi][0] = v.x + bi.x; gate[gi][1] = v.y + bi.y;
        gate[gi][2] = v.z + bi.z; gate[gi][3] = v.w + bi.w;
        float s = gate[gi][0] + gate[gi][1] + gate[gi][2] + gate[gi][3];
        float sq = gate[gi][0]*gate[gi][0] + gate[gi][1]*gate[gi][1]
                 + gate[gi][2]*gate[gi][2] + gate[gi][3]*gate[gi][3];
        block_reduce2(s, sq, sh, tid);
        float mean = s * (1.0f / H_DIM);
        float var  = (sq - (float)H_DIM * mean * mean) * (1.0f / (H_DIM - 1));
        var = fmaxf(var, 0.0f);
        float inv = 1.0f / (sqrtf(var) + EPS);
        float4 ga = gam4[gi * 256 + tid];
        float4 be = bet4[gi * 256 + tid];
        gate[gi][0] = ga.x * (gate[gi][0] - mean) * inv + be.x;
        gate[gi][1] = ga.y * (gate[gi][1] - mean) * inv + be.y;
        gate[gi][2] = ga.z * (gate[gi][2] - mean) * inv + be.z;
        gate[gi][3] = ga.w * (gate[gi][3] - mean) * inv + be.w;
    }

    float nc[4], og[4];
    {
        float4 cv4 = ((const float4*)(c + (size_t)b * H_DIM))[tid];
        float cvv[4] = { cv4.x, cv4.y, cv4.z, cv4.w };
        float s = 0.0f, sq = 0.0f;
#pragma unroll
        for (int r = 0; r < 4; r++) {
            float iv = gate[0][r];
            float fv = gate[1][r] + 1.0f;
            float gv = gate[2][r];
            og[r]    = gate[3][r];
            float v  = cvv[r] * sigmoidf_(fv) + sigmoidf_(iv) * tanhf_(gv);
            nc[r] = v;
            s += v; sq += v * v;
        }
        block_reduce2(s, sq, sh, tid);
        float mean = s * (1.0f / H_DIM);
        float var  = (sq - (float)H_DIM * mean * mean) * (1.0f / (H_DIM - 1));
        var = fmaxf(var, 0.0f);
        float inv = 1.0f / (sqrtf(var) + EPS);
        float4 gc = ((const float4*)gamma_c)[tid];
        float4 bc = ((const float4*)beta_c)[tid];
        float gcv[4] = { gc.x, gc.y, gc.z, gc.w };
        float bcv[4] = { bc.x, bc.y, bc.z, bc.w };
        float4 oc, oh;
        float* ocp = &oc.x;
        float* ohp = &oh.x;
#pragma unroll
        for (int r = 0; r < 4; r++) {
            float ncv = gcv[r] * (nc[r] - mean) * inv + bcv[r];
            ocp[r] = ncv;
            ohp[r] = tanhf_(ncv) * sigmoidf_(og[r]);
        }
        ((float4*)(out_c + (size_t)b * H_DIM))[tid] = oc;
        ((float4*)(out_h + (size_t)b * H_DIM))[tid] = oh;
    }
}

// ---------------------------------------------------------------------------
// Launch
// ---------------------------------------------------------------------------
extern "C" void kernel_launch(void* const* d_in, const int* in_sizes, int n_in,
                              void* d_out, int out_size)
{
    const float* x          = (const float*)d_in[0];
    const float* h          = (const float*)d_in[1];
    const float* c          = (const float*)d_in[2];
    const float* w_ih       = (const float*)d_in[3];
    const float* b_ih       = (const float*)d_in[4];
    const float* w_hh       = (const float*)d_in[5];
    const float* gamma_ifgo = (const float*)d_in[6];
    const float* beta_ifgo  = (const float*)d_in[7];
    const float* gamma_c    = (const float*)d_in[8];
    const float* beta_c     = (const float*)d_in[9];

    float* out_h = (float*)d_out;
    float* out_c = (float*)d_out + (size_t)B_DIM * H_DIM;

    cudaFuncSetAttribute(lstm_gemm_f16,
                         cudaFuncAttributeMaxDynamicSharedMemorySize, SMEM_TOTAL);

    conv_A<<<16384, 256>>>(x, h);
    conv_B<<<8192, 256>>>(w_ih, w_hh);

    dim3 grid(N_DIM / TN, B_DIM / TM);  // (16, 64)
    lstm_gemm_f16<<<grid, 256, SMEM_TOTAL>>>();

    lstm_epilogue_kernel<<<B_DIM, 256>>>(c, b_ih, gamma_ifgo, beta_ifgo,
                                         gamma_c, beta_c, out_h, out_c);
}

// round 5
// speedup vs baseline: 5.2853x; 1.0673x over previous
#include <cuda_runtime.h>
#include <cuda_fp16.h>
#include <math.h>
#include <stdint.h>

#define B_DIM 8192
#define IN_DIM 1024
#define H_DIM 1024
#define N_DIM 4096
#define K_DIM 2048
#define EPS 1e-6f

// GEMM tiling
#define TM 128
#define TN 256
#define KT 32                       // halves per k-tile (2 ksteps of k16)
#define KTILES (K_DIM / KT)         // 64
#define ROW_B 80                    // bytes per smem row: 64 data + 16 pad
#define A_STAGE_B (TM * ROW_B)      // 10240
#define B_STAGE_B (TN * ROW_B)      // 20480
#define STAGE_B (A_STAGE_B + B_STAGE_B)   // 30720
#define SMEM_TOTAL (3 * STAGE_B)          // 92160

// Scratch: fp16 operands (packed K=2048) + fp32 GEMM output
__device__ __half g_A[(size_t)B_DIM * K_DIM];   // 33.5 MB
__device__ __half g_B[(size_t)N_DIM * K_DIM];   // 16.8 MB
__device__ float  g_v[(size_t)B_DIM * N_DIM];   // 134 MB

// ---------------------------------------------------------------------------
// Helpers
// ---------------------------------------------------------------------------
__device__ __forceinline__ uint32_t smem_u32(const void* p) {
    uint32_t a;
    asm("{ .reg .u64 t; cvta.to.shared.u64 t, %1; cvt.u32.u64 %0, t; }"
        : "=r"(a) : "l"(p));
    return a;
}
__device__ __forceinline__ void cp16(uint32_t smem, const void* g) {
    asm volatile("cp.async.cg.shared.global [%0], [%1], 16;"
                 :: "r"(smem), "l"(g));
}
#define LDSM_X4(r0, r1, r2, r3, addr)                                        \
    asm volatile("ldmatrix.sync.aligned.m8n8.x4.shared.b16 {%0,%1,%2,%3}, [%4];" \
                 : "=r"(r0), "=r"(r1), "=r"(r2), "=r"(r3) : "r"(addr))

#define MMA_F16(d, a, b)                                                     \
    asm volatile(                                                            \
        "mma.sync.aligned.m16n8k16.row.col.f32.f16.f16.f32 "                 \
        "{%0,%1,%2,%3}, {%4,%5,%6,%7}, {%8,%9}, {%0,%1,%2,%3};"              \
        : "+f"((d)[0]), "+f"((d)[1]), "+f"((d)[2]), "+f"((d)[3])             \
        : "r"((a)[0]), "r"((a)[1]), "r"((a)[2]), "r"((a)[3]),                \
          "r"((b)[0]), "r"((b)[1]))

// ---------------------------------------------------------------------------
// fp16 conversion pre-pass (merged): pack x|h -> g_A, w_ih|w_hh -> g_B
// Blocks [0, 16384): A units; [16384, 24576): B units. One float4 per thread.
// ---------------------------------------------------------------------------
__global__ __launch_bounds__(256)
void conv_AB(const float* __restrict__ x, const float* __restrict__ h,
             const float* __restrict__ w_ih, const float* __restrict__ w_hh)
{
    if (blockIdx.x < 16384) {
        size_t idx = (size_t)blockIdx.x * 256 + threadIdx.x;
        int r = (int)(idx >> 9);
        int k = ((int)idx & 511) * 4;
        const float* src = (k < IN_DIM) ? (x + (size_t)r * IN_DIM + k)
                                        : (h + (size_t)r * H_DIM + (k - IN_DIM));
        float4 v = *(const float4*)src;
        *(__half2*)(g_A + (size_t)r * K_DIM + k)     = __floats2half2_rn(v.x, v.y);
        *(__half2*)(g_A + (size_t)r * K_DIM + k + 2) = __floats2half2_rn(v.z, v.w);
    } else {
        size_t idx = (size_t)(blockIdx.x - 16384) * 256 + threadIdx.x;
        int r = (int)(idx >> 9);
        int k = ((int)idx & 511) * 4;
        const float* src = (k < IN_DIM) ? (w_ih + (size_t)r * IN_DIM + k)
                                        : (w_hh + (size_t)r * H_DIM + (k - IN_DIM));
        float4 v = *(const float4*)src;
        *(__half2*)(g_B + (size_t)r * K_DIM + k)     = __floats2half2_rn(v.x, v.y);
        *(__half2*)(g_B + (size_t)r * K_DIM + k + 2) = __floats2half2_rn(v.z, v.w);
    }
}

// ---------------------------------------------------------------------------
// fp16 mma.sync GEMM: v = A @ B^T   (M=8192, N=4096, K=2048)
// CTA 128x256, KT=32 (2 ksteps), 3-stage cp.async, ldmatrix fragment loads.
// 8 warps, warp grid 2(M) x 4(N), warp tile 64x64 -> 4x8 m16n8k16 per kstep.
// ---------------------------------------------------------------------------
__device__ __forceinline__ void load_stage(int kt, int s, int tid,
                                           uint32_t sbase, int bm, int bn)
{
    uint32_t sA = sbase + s * STAGE_B;
    uint32_t sB = sA + A_STAGE_B;
    int k0 = kt * KT;
    const __half* ga = g_A + (size_t)bm * K_DIM + k0;
    const __half* gb = g_B + (size_t)bn * K_DIM + k0;
#pragma unroll
    for (int i = 0; i < 2; i++) {               // A: 512 16B units
        int u = tid + i * 256;
        int row = u >> 2, q = u & 3;
        cp16(sA + (uint32_t)(row * ROW_B + q * 16),
             ga + (size_t)row * K_DIM + q * 8);
    }
#pragma unroll
    for (int i = 0; i < 4; i++) {               // B: 1024 16B units
        int u = tid + i * 256;
        int row = u >> 2, q = u & 3;
        cp16(sB + (uint32_t)(row * ROW_B + q * 16),
             gb + (size_t)row * K_DIM + q * 8);
    }
    asm volatile("cp.async.commit_group;" ::: "memory");
}

__global__ __launch_bounds__(256, 1)
void lstm_gemm_f16()
{
    extern __shared__ __align__(128) char smem[];
    uint32_t sbase = smem_u32(smem);
    const int tid = threadIdx.x;
    const int wid = tid >> 5, lane = tid & 31;
    const int g = lane >> 2, c = lane & 3;
    const int warpM = (wid & 1) * 64;
    const int warpN = (wid >> 1) * 64;
    const int bn = blockIdx.x * TN;
    const int bm = blockIdx.y * TM;

    // ldmatrix per-lane offsets (bytes within a stage)
    const int q  = lane >> 3;       // 0..3 (matrix index)
    const int rr = lane & 7;        // row within 8x8
    const uint32_t laneA = (uint32_t)(((q & 1) * 8 + rr) * ROW_B + (q >> 1) * 16);
    const uint32_t laneB = (uint32_t)(((q >> 1) * 8 + rr) * ROW_B + (q & 1) * 16);

    float acc[4][8][4];
#pragma unroll
    for (int mt = 0; mt < 4; mt++)
#pragma unroll
        for (int nt = 0; nt < 8; nt++)
#pragma unroll
            for (int r = 0; r < 4; r++)
                acc[mt][nt][r] = 0.0f;

    load_stage(0, 0, tid, sbase, bm, bn);
    load_stage(1, 1, tid, sbase, bm, bn);

    for (int kt = 0; kt < KTILES; kt++) {
        int s = kt % 3;
        if (kt < KTILES - 1) asm volatile("cp.async.wait_group 1;" ::: "memory");
        else                 asm volatile("cp.async.wait_group 0;" ::: "memory");
        // This barrier both publishes stage s (loaded) and guarantees all
        // warps finished computing on the stage that load_stage below reuses.
        __syncthreads();

        if (kt + 2 < KTILES)
            load_stage(kt + 2, (kt + 2) % 3, tid, sbase, bm, bn);

        uint32_t stA = sbase + s * STAGE_B;
        uint32_t stB = stA + A_STAGE_B;

#pragma unroll
        for (int ks = 0; ks < 2; ks++) {
            uint32_t a[4][4], b[4][4];
#pragma unroll
            for (int mt = 0; mt < 4; mt++) {
                uint32_t addr = stA + (uint32_t)((warpM + mt * 16) * ROW_B
                                                 + ks * 32) + laneA;
                LDSM_X4(a[mt][0], a[mt][1], a[mt][2], a[mt][3], addr);
            }
#pragma unroll
            for (int np = 0; np < 4; np++) {
                uint32_t addr = stB + (uint32_t)((warpN + np * 16) * ROW_B
                                                 + ks * 32) + laneB;
                LDSM_X4(b[np][0], b[np][1], b[np][2], b[np][3], addr);
            }
#pragma unroll
            for (int mt = 0; mt < 4; mt++)
#pragma unroll
                for (int nt = 0; nt < 8; nt++) {
                    uint32_t bf[2] = { b[nt >> 1][(nt & 1) * 2],
                                       b[nt >> 1][(nt & 1) * 2 + 1] };
                    MMA_F16(acc[mt][nt], a[mt], bf);
                }
        }
        // no trailing __syncthreads: next iteration's barrier provides the
        // ordering before that iteration's load_stage overwrites this stage.
    }

    // Store C
#pragma unroll
    for (int mt = 0; mt < 4; mt++) {
        int r0 = bm + warpM + mt * 16 + g;
#pragma unroll
        for (int nt = 0; nt < 8; nt++) {
            int cn = bn + warpN + nt * 8 + 2 * c;
            *(float2*)(g_v + (size_t)r0 * N_DIM + cn)
                = make_float2(acc[mt][nt][0], acc[mt][nt][1]);
            *(float2*)(g_v + (size_t)(r0 + 8) * N_DIM + cn)
                = make_float2(acc[mt][nt][2], acc[mt][nt][3]);
        }
    }
}

// ---------------------------------------------------------------------------
// Epilogue: batched loads up-front (high MLP), 2-barrier combined reduction
// for all 4 gate (sum,sumsq), 2-barrier reduction for cell LN. MUFU math.
// ---------------------------------------------------------------------------
__device__ __forceinline__ float sigmoidf_(float v) {
    return 1.0f / (1.0f + __expf(-v));
}
__device__ __forceinline__ float tanhf_(float v) {
    return 2.0f / (1.0f + __expf(-2.0f * v)) - 1.0f;
}

__global__ __launch_bounds__(256, 4)
void lstm_epilogue_kernel(const float* __restrict__ c,
                          const float* __restrict__ b_ih,
                          const float* __restrict__ gamma_ifgo,
                          const float* __restrict__ beta_ifgo,
                          const float* __restrict__ gamma_c,
                          const float* __restrict__ beta_c,
                          float* __restrict__ out_h,
                          float* __restrict__ out_c)
{
    __shared__ float sh[72];

    const int b    = blockIdx.x;
    const int tid  = threadIdx.x;
    const int lane = tid & 31, warp = tid >> 5;

    const float4* vrow = (const float4*)&g_v[(size_t)b * N_DIM];
    const float4* bih4 = (const float4*)b_ih;

    // ---- load all 4 gates + bias, accumulate per-gate (sum, sumsq) ----
    float gate[4][4];
    float red[8];
#pragma unroll
    for (int gi = 0; gi < 4; gi++) {
        float4 v  = vrow[gi * 256 + tid];
        float4 bi = bih4[gi * 256 + tid];
        gate[gi][0] = v.x + bi.x; gate[gi][1] = v.y + bi.y;
        gate[gi][2] = v.z + bi.z; gate[gi][3] = v.w + bi.w;
        red[2 * gi]     = gate[gi][0] + gate[gi][1] + gate[gi][2] + gate[gi][3];
        red[2 * gi + 1] = gate[gi][0] * gate[gi][0] + gate[gi][1] * gate[gi][1]
                        + gate[gi][2] * gate[gi][2] + gate[gi][3] * gate[gi][3];
    }

    // ---- combined reduction of 8 values across 256 threads (2 barriers) ----
#pragma unroll
    for (int v = 0; v < 8; v++)
#pragma unroll
        for (int off = 16; off > 0; off >>= 1)
            red[v] += __shfl_down_sync(0xFFFFFFFFu, red[v], off);
    if (lane == 0) {
#pragma unroll
        for (int v = 0; v < 8; v++) sh[warp * 8 + v] = red[v];
    }
    __syncthreads();
    if (tid < 32) {
        int v = tid & 7, p = tid >> 3;            // p = 0..3
        float t = sh[p * 8 + v] + sh[(p + 4) * 8 + v];
        t += __shfl_down_sync(0xFFFFFFFFu, t, 8);
        t += __shfl_down_sync(0xFFFFFFFFu, t, 16);
        if (tid < 8) sh[64 + tid] = t;            // totals: [2gi]=sum,[2gi+1]=sq
    }
    __syncthreads();

    // ---- apply gate LayerNorms ----
    const float4* gam4 = (const float4*)gamma_ifgo;
    const float4* bet4 = (const float4*)beta_ifgo;
#pragma unroll
    for (int gi = 0; gi < 4; gi++) {
        float s  = sh[64 + 2 * gi];
        float sq = sh[64 + 2 * gi + 1];
        float mean = s * (1.0f / H_DIM);
        float var  = (sq - (float)H_DIM * mean * mean) * (1.0f / (H_DIM - 1));
        var = fmaxf(var, 0.0f);
        float inv = 1.0f / (sqrtf(var) + EPS);
        float4 ga = gam4[gi * 256 + tid];
        float4 be = bet4[gi * 256 + tid];
        gate[gi][0] = ga.x * (gate[gi][0] - mean) * inv + be.x;
        gate[gi][1] = ga.y * (gate[gi][1] - mean) * inv + be.y;
        gate[gi][2] = ga.z * (gate[gi][2] - mean) * inv + be.z;
        gate[gi][3] = ga.w * (gate[gi][3] - mean) * inv + be.w;
    }

    // ---- LSTM pointwise ----
    float nc[4], og[4];
    float4 cv4 = ((const float4*)(c + (size_t)b * H_DIM))[tid];
    float cvv[4] = { cv4.x, cv4.y, cv4.z, cv4.w };
    float s = 0.0f, sq = 0.0f;
#pragma unroll
    for (int r = 0; r < 4; r++) {
        float iv = gate[0][r];
        float fv = gate[1][r] + 1.0f;
        float gv = gate[2][r];
        og[r]    = gate[3][r];
        float v  = cvv[r] * sigmoidf_(fv) + sigmoidf_(iv) * tanhf_(gv);
        nc[r] = v;
        s += v; sq += v * v;
    }

    // ---- cell LN reduction (2 barriers) ----
#pragma unroll
    for (int off = 16; off > 0; off >>= 1) {
        s  += __shfl_down_sync(0xFFFFFFFFu, s,  off);
        sq += __shfl_down_sync(0xFFFFFFFFu, sq, off);
    }
    if (lane == 0) { sh[warp] = s; sh[8 + warp] = sq; }
    __syncthreads();
    if (tid < 32) {
        float t = (tid < 16) ? sh[tid] : 0.0f;    // [0..7]=s, [8..15]=sq
        t += __shfl_down_sync(0xFFFFFFFFu, t, 4);
        t += __shfl_down_sync(0xFFFFFFFFu, t, 2);
        t += __shfl_down_sync(0xFFFFFFFFu, t, 1);
        if (tid == 0) sh[64] = t;                 // lane 0: sum of sh[0..7]
        if (tid == 8) sh[65] = t;                 // lane 8: sum of sh[8..15]
    }
    __syncthreads();
    {
        float mean = sh[64] * (1.0f / H_DIM);
        float var  = (sh[65] - (float)H_DIM * mean * mean) * (1.0f / (H_DIM - 1));
        var = fmaxf(var, 0.0f);
        float inv = 1.0f / (sqrtf(var) + EPS);
        float4 gc = ((const float4*)gamma_c)[tid];
        float4 bc = ((const float4*)beta_c)[tid];
        float gcv[4] = { gc.x, gc.y, gc.z, gc.w };
        float bcv[4] = { bc.x, bc.y, bc.z, bc.w };
        float4 oc, oh;
        float* ocp = &oc.x;
        float* ohp = &oh.x;
#pragma unroll
        for (int r = 0; r < 4; r++) {
            float ncv = gcv[r] * (nc[r] - mean) * inv + bcv[r];
            ocp[r] = ncv;
            ohp[r] = tanhf_(ncv) * sigmoidf_(og[r]);
        }
        ((float4*)(out_c + (size_t)b * H_DIM))[tid] = oc;
        ((float4*)(out_h + (size_t)b * H_DIM))[tid] = oh;
    }
}

// ---------------------------------------------------------------------------
// Launch
// ---------------------------------------------------------------------------
extern "C" void kernel_launch(void* const* d_in, const int* in_sizes, int n_in,
                              void* d_out, int out_size)
{
    const float* x          = (const float*)d_in[0];
    const float* h          = (const float*)d_in[1];
    const float* c          = (const float*)d_in[2];
    const float* w_ih       = (const float*)d_in[3];
    const float* b_ih       = (const float*)d_in[4];
    const float* w_hh       = (const float*)d_in[5];
    const float* gamma_ifgo = (const float*)d_in[6];
    const float* beta_ifgo  = (const float*)d_in[7];
    const float* gamma_c    = (const float*)d_in[8];
    const float* beta_c     = (const float*)d_in[9];

    float* out_h = (float*)d_out;
    float* out_c = (float*)d_out + (size_t)B_DIM * H_DIM;

    cudaFuncSetAttribute(lstm_gemm_f16,
                         cudaFuncAttributeMaxDynamicSharedMemorySize, SMEM_TOTAL);

    conv_AB<<<24576, 256>>>(x, h, w_ih, w_hh);

    dim3 grid(N_DIM / TN, B_DIM / TM);  // (16, 64)
    lstm_gemm_f16<<<grid, 256, SMEM_TOTAL>>>();

    lstm_epilogue_kernel<<<B_DIM, 256>>>(c, b_ih, gamma_ifgo, beta_ifgo,
                                         gamma_c, beta_c, out_h, out_c);
}